// round 7
// baseline (speedup 1.0000x reference)
#include <cuda_runtime.h>
#include <cuda_bf16.h>
#include <math.h>

// Problem shape (fixed by dataset): N=500000, D=128, K=2048
#define MAXN   500000
#define DIM    128
#define NBINS  65536
#define CAP    6144
#define MAXK   2048
#define ROWS_PER_WARP 8

static __device__ unsigned int        g_keys[MAXN];
static __device__ unsigned int        g_hist[NBINS];
static __device__ unsigned int        g_coarse[256];
static __device__ unsigned int        g_counter;
static __device__ unsigned int        g_done;
static __device__ unsigned int        g_thresh;
static __device__ unsigned long long  g_cand[CAP];

// order-preserving float -> u32 key
__device__ __forceinline__ unsigned int fkey(float f) {
    unsigned int b = __float_as_uint(f);
    return (b & 0x80000000u) ? ~b : (b | 0x80000000u);
}
__device__ __forceinline__ float fdec(unsigned int k) {
    unsigned int b = (k & 0x80000000u) ? (k ^ 0x80000000u) : ~k;
    return __uint_as_float(b);
}

// ---------------------------------------------------------------- kernels 1-3 (zero split so score = launch index 3)
__global__ void zeroA_kernel() {   // <<<32,256>>> : hist[0:32768)
    int i = blockIdx.x * blockDim.x + threadIdx.x;
    reinterpret_cast<uint4*>(g_hist)[i] = make_uint4(0u, 0u, 0u, 0u);
}
__global__ void zeroB_kernel() {   // <<<32,256>>> : hist[32768:65536)
    int i = blockIdx.x * blockDim.x + threadIdx.x;
    reinterpret_cast<uint4*>(g_hist)[8192 + i] = make_uint4(0u, 0u, 0u, 0u);
}
__global__ void zeroC_kernel() {   // <<<1,1>>>
    g_counter = 0u; g_done = 0u;
}

// ---------------------------------------------------------------- kernel 4
// persistent warps; 8 rows/iter; packed tree reduction (9 SHFL per 8 rows)
__global__ void score_kernel(const float* __restrict__ x,
                             const float* __restrict__ p, int n) {
    const int lane   = threadIdx.x & 31;
    const int wid    = (blockIdx.x * blockDim.x + threadIdx.x) >> 5;
    const int nwarps = (gridDim.x * blockDim.x) >> 5;

    float4 p4 = reinterpret_cast<const float4*>(p)[lane];
    float sq = p4.x * p4.x + p4.y * p4.y + p4.z * p4.z + p4.w * p4.w;
    #pragma unroll
    for (int off = 16; off > 0; off >>= 1)
        sq += __shfl_xor_sync(0xFFFFFFFFu, sq, off);
    const float inv = rsqrtf(sq);

    const bool b4 = (lane & 16) != 0;
    const bool b3 = (lane & 8)  != 0;
    const bool b2 = (lane & 4)  != 0;

    const float4* __restrict__ x4p = reinterpret_cast<const float4*>(x);

    for (long long base = (long long)wid * ROWS_PER_WARP; base < n;
         base += (long long)nwarps * ROWS_PER_WARP) {

        float4 v[ROWS_PER_WARP];
        #pragma unroll
        for (int r = 0; r < ROWS_PER_WARP; r++) {
            long long row = base + r;
            v[r] = (row < n) ? __ldcs(&x4p[row * 32 + lane])
                             : make_float4(0.f, 0.f, 0.f, 0.f);
        }
        float d[ROWS_PER_WARP];
        #pragma unroll
        for (int r = 0; r < ROWS_PER_WARP; r++) {
            d[r] = fmaf(v[r].x, p4.x, fmaf(v[r].y, p4.y,
                   fmaf(v[r].z, p4.z, v[r].w * p4.w)));
        }

        // ---- packed tree reduction: 8 regs -> 1 reg, 9 shuffles total ----
        // stage 1 (offset 16): keep row (2k + b4) locally
        float e[4];
        #pragma unroll
        for (int k = 0; k < 4; k++) {
            float keep = b4 ? d[2*k+1] : d[2*k];
            float send = b4 ? d[2*k]   : d[2*k+1];
            e[k] = keep + __shfl_xor_sync(0xFFFFFFFFu, send, 16);
        }
        // stage 2 (offset 8): e-index (2j + b3); row = 4j + 2*b3 + b4
        float f[2];
        #pragma unroll
        for (int j = 0; j < 2; j++) {
            float keep = b3 ? e[2*j+1] : e[2*j];
            float send = b3 ? e[2*j]   : e[2*j+1];
            f[j] = keep + __shfl_xor_sync(0xFFFFFFFFu, send, 8);
        }
        // stage 3 (offset 4): row = 4*b2 + 2*b3 + b4
        float g;
        {
            float keep = b2 ? f[1] : f[0];
            float send = b2 ? f[0] : f[1];
            g = keep + __shfl_xor_sync(0xFFFFFFFFu, send, 4);
        }
        // stages 4-5: finish within 4-lane groups
        g += __shfl_xor_sync(0xFFFFFFFFu, g, 2);
        g += __shfl_xor_sync(0xFFFFFFFFu, g, 1);

        // publish: lanes 4m own row bitrev3(m)
        if ((lane & 3) == 0) {
            int m = lane >> 2;
            int r = ((m & 1) << 2) | (m & 2) | ((m >> 2) & 1);
            long long row = base + r;
            if (row < n) {
                unsigned int key = fkey(g * inv);
                g_keys[row] = key;
                atomicAdd(&g_hist[key >> 16], 1u);
            }
        }
    }
}

// ---------------------------------------------------------------- kernel 5
// fused coarse sums + threshold search (last-block-done pattern); <<<256,256>>>
__global__ void coarse_thresh_kernel(int kk) {
    __shared__ unsigned int sh[256];
    __shared__ unsigned int suf[256];
    __shared__ int s_last;
    __shared__ int s_ch;
    __shared__ unsigned int s_above;

    int t = threadIdx.x;
    int b = blockIdx.x;

    sh[t] = g_hist[b * 256 + t];
    __syncthreads();
    #pragma unroll
    for (int off = 128; off >= 1; off >>= 1) {
        if (t < off) sh[t] += sh[t + off];
        __syncthreads();
    }
    if (t == 0) {
        g_coarse[b] = sh[0];
        __threadfence();
        unsigned int d = atomicAdd(&g_done, 1u);
        s_last = (d == 255u);
    }
    __syncthreads();
    if (!s_last) return;

    __threadfence();
    suf[t] = g_coarse[t];
    __syncthreads();
    #pragma unroll
    for (int off = 1; off < 256; off <<= 1) {
        unsigned int u = (t + off < 256) ? suf[t + off] : 0u;
        __syncthreads();
        suf[t] += u;
        __syncthreads();
    }
    if (suf[t] >= (unsigned int)kk &&
        (t == 255 || suf[t + 1] < (unsigned int)kk)) {
        s_ch = t;
        s_above = (t == 255) ? 0u : suf[t + 1];
    }
    __syncthreads();

    int ch = s_ch;
    unsigned int above = s_above;

    sh[t] = g_hist[ch * 256 + t];
    __syncthreads();
    #pragma unroll
    for (int off = 1; off < 256; off <<= 1) {
        unsigned int u = (t + off < 256) ? sh[t + off] : 0u;
        __syncthreads();
        sh[t] += u;
        __syncthreads();
    }
    if (above + sh[t] >= (unsigned int)kk &&
        (t == 255 || above + sh[t + 1] < (unsigned int)kk)) {
        g_thresh = ((unsigned int)(ch * 256 + t)) << 16;
    }
}

// ---------------------------------------------------------------- kernel 6
// compact: one uint4 per thread, warp-aggregated atomic
__global__ void compact_kernel(int n) {
    const unsigned int thr = g_thresh;
    const int nq = n >> 2;                       // n % 4 == 0
    int i = blockIdx.x * blockDim.x + threadIdx.x;
    int lane = threadIdx.x & 31;

    uint4 k = (i < nq) ? reinterpret_cast<const uint4*>(g_keys)[i]
                       : make_uint4(0u, 0u, 0u, 0u);
    unsigned int kv[4] = {k.x, k.y, k.z, k.w};
    unsigned int cnt = 0;
    #pragma unroll
    for (int e = 0; e < 4; e++) cnt += (kv[e] >= thr);

    if (__ballot_sync(0xFFFFFFFFu, cnt > 0) == 0u) return;

    // warp inclusive scan of cnt
    unsigned int pre = cnt;
    #pragma unroll
    for (int off = 1; off < 32; off <<= 1) {
        unsigned int u = __shfl_up_sync(0xFFFFFFFFu, pre, off);
        if (lane >= off) pre += u;
    }
    unsigned int tot = __shfl_sync(0xFFFFFFFFu, pre, 31);
    unsigned int excl = pre - cnt;

    unsigned int base = 0;
    if (lane == 31) base = atomicAdd(&g_counter, tot);
    base = __shfl_sync(0xFFFFFFFFu, base, 31);

    unsigned int pos = base + excl;
    unsigned int bi = (unsigned int)(i << 2);
    #pragma unroll
    for (int e = 0; e < 4; e++) {
        if (kv[e] >= thr) {
            if (pos < CAP)
                g_cand[pos] = ((unsigned long long)kv[e] << 32) |
                              (0xFFFFFFFFull - (bi + e));
            pos++;
        }
    }
}

// ---------------------------------------------------------------- kernel 7
// fused rank-by-counting + gather: warp per candidate; writes out[rank] row
__global__ void rank_gather_kernel(const float* __restrict__ x,
                                   float* __restrict__ out, int kk) {
    unsigned int C = g_counter; if (C > CAP) C = CAP;
    int w    = (blockIdx.x * blockDim.x + threadIdx.x) >> 5;
    int lane = threadIdx.x & 31;
    if (w >= (int)C) return;

    unsigned long long me = g_cand[w];
    int cnt = 0;
    int j = lane;
    for (; j + 96 < (int)C; j += 128) {
        unsigned long long a = g_cand[j];
        unsigned long long b = g_cand[j + 32];
        unsigned long long c = g_cand[j + 64];
        unsigned long long d = g_cand[j + 96];
        cnt += (a > me) + (b > me) + (c > me) + (d > me);
    }
    for (; j < (int)C; j += 32)
        cnt += (g_cand[j] > me);

    #pragma unroll
    for (int off = 16; off > 0; off >>= 1)
        cnt += __shfl_xor_sync(0xFFFFFFFFu, cnt, off);   // all lanes get rank

    if (cnt < kk) {
        unsigned int key = (unsigned int)(me >> 32);
        unsigned int idx = 0xFFFFFFFFu - (unsigned int)(me & 0xFFFFFFFFull);
        float tv = tanhf(fdec(key));
        const float4* __restrict__ src = reinterpret_cast<const float4*>(x) +
                                         (size_t)idx * 32;
        float4* __restrict__ dst = reinterpret_cast<float4*>(out) +
                                   (size_t)cnt * 32;
        float4 v = src[lane];
        v.x *= tv; v.y *= tv; v.z *= tv; v.w *= tv;
        dst[lane] = v;
    }
}

// ----------------------------------------------------------------
extern "C" void kernel_launch(void* const* d_in, const int* in_sizes, int n_in,
                              void* d_out, int out_size) {
    const float* x = (const float*)d_in[0];
    const float* p = (const float*)d_in[1];
    float* out = (float*)d_out;

    int n  = in_sizes[0] / DIM;      // 500000
    int kk = out_size / DIM;         // 2048

    zeroA_kernel<<<32, 256>>>();
    zeroB_kernel<<<32, 256>>>();
    zeroC_kernel<<<1, 1>>>();
    score_kernel<<<148 * 8, 256>>>(x, p, n);     // launch index 3 -> profiled
    coarse_thresh_kernel<<<256, 256>>>(kk);
    int nq = n >> 2;
    compact_kernel<<<(nq + 255) / 256, 256>>>(n);
    rank_gather_kernel<<<(CAP * 32) / 256, 256>>>(x, out, kk);
}

// round 9
// speedup vs baseline: 1.0274x; 1.0274x over previous
#include <cuda_runtime.h>
#include <cuda_bf16.h>
#include <math.h>

// Problem shape (fixed by dataset): N=500000, D=128, K=2048
#define MAXN   500000
#define DIM    128
#define NBINS  65536
#define CAP    6144
#define MAXK   2048
#define ROWS_PER_WARP 8

static __device__ unsigned int        g_keys[MAXN];
static __device__ unsigned int        g_hist[NBINS];
static __device__ unsigned int        g_coarse[256];
static __device__ unsigned int        g_counter;
static __device__ unsigned int        g_done;
static __device__ unsigned int        g_thresh;
static __device__ unsigned long long  g_cand[CAP];

// order-preserving float -> u32 key
__device__ __forceinline__ unsigned int fkey(float f) {
    unsigned int b = __float_as_uint(f);
    return (b & 0x80000000u) ? ~b : (b | 0x80000000u);
}
__device__ __forceinline__ float fdec(unsigned int k) {
    unsigned int b = (k & 0x80000000u) ? (k ^ 0x80000000u) : ~k;
    return __uint_as_float(b);
}

// ---------------------------------------------------------------- kernels 1-3 (zero split so score = launch index 3)
__global__ void zeroA_kernel() {   // <<<32,256>>> : hist[0:32768)
    int i = blockIdx.x * blockDim.x + threadIdx.x;
    reinterpret_cast<uint4*>(g_hist)[i] = make_uint4(0u, 0u, 0u, 0u);
}
__global__ void zeroB_kernel() {   // <<<32,256>>> : hist[32768:65536)
    int i = blockIdx.x * blockDim.x + threadIdx.x;
    reinterpret_cast<uint4*>(g_hist)[8192 + i] = make_uint4(0u, 0u, 0u, 0u);
}
__global__ void zeroC_kernel() {   // <<<1,1>>>
    g_counter = 0u; g_done = 0u;
}

// ---------------------------------------------------------------- kernel 4
// persistent warps; 8 rows/iter; 2 blocks/SM so ptxas can front-batch
// all 8 LDG.128 (needs ~64+ regs); packed tree reduction (9 SHFL / 8 rows)
__global__ void __launch_bounds__(256, 2)
score_kernel(const float* __restrict__ x,
             const float* __restrict__ p, int n) {
    const int lane   = threadIdx.x & 31;
    const int wid    = (blockIdx.x * blockDim.x + threadIdx.x) >> 5;
    const int nwarps = (gridDim.x * blockDim.x) >> 5;

    float4 p4 = reinterpret_cast<const float4*>(p)[lane];
    float sq = p4.x * p4.x + p4.y * p4.y + p4.z * p4.z + p4.w * p4.w;
    #pragma unroll
    for (int off = 16; off > 0; off >>= 1)
        sq += __shfl_xor_sync(0xFFFFFFFFu, sq, off);
    const float inv = rsqrtf(sq);

    const bool b4 = (lane & 16) != 0;
    const bool b3 = (lane & 8)  != 0;
    const bool b2 = (lane & 4)  != 0;

    const float4* __restrict__ x4p = reinterpret_cast<const float4*>(x);
    const long long stride = (long long)nwarps * ROWS_PER_WARP;

    for (long long base = (long long)wid * ROWS_PER_WARP; base < n;
         base += stride) {

        float4 v[ROWS_PER_WARP];
        const float4* __restrict__ ptr = x4p + base * 32 + lane;

        if (base + ROWS_PER_WARP <= n) {
            // fast path: 8 unconditional, independent loads -> front-batched
            #pragma unroll
            for (int r = 0; r < ROWS_PER_WARP; r++)
                v[r] = __ldcs(ptr + r * 32);
        } else {
            #pragma unroll
            for (int r = 0; r < ROWS_PER_WARP; r++)
                v[r] = (base + r < n) ? __ldcs(ptr + r * 32)
                                      : make_float4(0.f, 0.f, 0.f, 0.f);
        }

        float d[ROWS_PER_WARP];
        #pragma unroll
        for (int r = 0; r < ROWS_PER_WARP; r++) {
            d[r] = fmaf(v[r].x, p4.x, fmaf(v[r].y, p4.y,
                   fmaf(v[r].z, p4.z, v[r].w * p4.w)));
        }

        // ---- packed tree reduction: 8 regs -> 1 reg, 9 shuffles total ----
        float e[4];
        #pragma unroll
        for (int k = 0; k < 4; k++) {
            float keep = b4 ? d[2*k+1] : d[2*k];
            float send = b4 ? d[2*k]   : d[2*k+1];
            e[k] = keep + __shfl_xor_sync(0xFFFFFFFFu, send, 16);
        }
        float f[2];
        #pragma unroll
        for (int j = 0; j < 2; j++) {
            float keep = b3 ? e[2*j+1] : e[2*j];
            float send = b3 ? e[2*j]   : e[2*j+1];
            f[j] = keep + __shfl_xor_sync(0xFFFFFFFFu, send, 8);
        }
        float g;
        {
            float keep = b2 ? f[1] : f[0];
            float send = b2 ? f[0] : f[1];
            g = keep + __shfl_xor_sync(0xFFFFFFFFu, send, 4);
        }
        g += __shfl_xor_sync(0xFFFFFFFFu, g, 2);
        g += __shfl_xor_sync(0xFFFFFFFFu, g, 1);

        // publish: lanes 4m own row bitrev3(m)
        if ((lane & 3) == 0) {
            int m = lane >> 2;
            int r = ((m & 1) << 2) | (m & 2) | ((m >> 2) & 1);
            long long row = base + r;
            if (row < n) {
                unsigned int key = fkey(g * inv);
                g_keys[row] = key;
                atomicAdd(&g_hist[key >> 16], 1u);
            }
        }
    }
}

// ---------------------------------------------------------------- kernel 5
// fused coarse sums + threshold search (last-block-done pattern); <<<256,256>>>
__global__ void coarse_thresh_kernel(int kk) {
    __shared__ unsigned int sh[256];
    __shared__ unsigned int suf[256];
    __shared__ int s_last;
    __shared__ int s_ch;
    __shared__ unsigned int s_above;

    int t = threadIdx.x;
    int b = blockIdx.x;

    sh[t] = g_hist[b * 256 + t];
    __syncthreads();
    #pragma unroll
    for (int off = 128; off >= 1; off >>= 1) {
        if (t < off) sh[t] += sh[t + off];
        __syncthreads();
    }
    if (t == 0) {
        g_coarse[b] = sh[0];
        __threadfence();
        unsigned int d = atomicAdd(&g_done, 1u);
        s_last = (d == 255u);
    }
    __syncthreads();
    if (!s_last) return;

    __threadfence();
    suf[t] = g_coarse[t];
    __syncthreads();
    #pragma unroll
    for (int off = 1; off < 256; off <<= 1) {
        unsigned int u = (t + off < 256) ? suf[t + off] : 0u;
        __syncthreads();
        suf[t] += u;
        __syncthreads();
    }
    if (suf[t] >= (unsigned int)kk &&
        (t == 255 || suf[t + 1] < (unsigned int)kk)) {
        s_ch = t;
        s_above = (t == 255) ? 0u : suf[t + 1];
    }
    __syncthreads();

    int ch = s_ch;
    unsigned int above = s_above;

    sh[t] = g_hist[ch * 256 + t];
    __syncthreads();
    #pragma unroll
    for (int off = 1; off < 256; off <<= 1) {
        unsigned int u = (t + off < 256) ? sh[t + off] : 0u;
        __syncthreads();
        sh[t] += u;
        __syncthreads();
    }
    if (above + sh[t] >= (unsigned int)kk &&
        (t == 255 || above + sh[t + 1] < (unsigned int)kk)) {
        g_thresh = ((unsigned int)(ch * 256 + t)) << 16;
    }
}

// ---------------------------------------------------------------- kernel 6
// compact: one uint4 per thread, warp-aggregated atomic
__global__ void compact_kernel(int n) {
    const unsigned int thr = g_thresh;
    const int nq = n >> 2;                       // n % 4 == 0
    int i = blockIdx.x * blockDim.x + threadIdx.x;
    int lane = threadIdx.x & 31;

    uint4 k = (i < nq) ? reinterpret_cast<const uint4*>(g_keys)[i]
                       : make_uint4(0u, 0u, 0u, 0u);
    unsigned int kv[4] = {k.x, k.y, k.z, k.w};
    unsigned int cnt = 0;
    #pragma unroll
    for (int e = 0; e < 4; e++) cnt += (kv[e] >= thr);

    if (__ballot_sync(0xFFFFFFFFu, cnt > 0) == 0u) return;

    unsigned int pre = cnt;
    #pragma unroll
    for (int off = 1; off < 32; off <<= 1) {
        unsigned int u = __shfl_up_sync(0xFFFFFFFFu, pre, off);
        if (lane >= off) pre += u;
    }
    unsigned int tot = __shfl_sync(0xFFFFFFFFu, pre, 31);
    unsigned int excl = pre - cnt;

    unsigned int base = 0;
    if (lane == 31) base = atomicAdd(&g_counter, tot);
    base = __shfl_sync(0xFFFFFFFFu, base, 31);

    unsigned int pos = base + excl;
    unsigned int bi = (unsigned int)(i << 2);
    #pragma unroll
    for (int e = 0; e < 4; e++) {
        if (kv[e] >= thr) {
            if (pos < CAP)
                g_cand[pos] = ((unsigned long long)kv[e] << 32) |
                              (0xFFFFFFFFull - (bi + e));
            pos++;
        }
    }
}

// ---------------------------------------------------------------- kernel 7
// fused rank-by-counting + gather: warp per candidate; writes out[rank] row
__global__ void rank_gather_kernel(const float* __restrict__ x,
                                   float* __restrict__ out, int kk) {
    unsigned int C = g_counter; if (C > CAP) C = CAP;
    int w    = (blockIdx.x * blockDim.x + threadIdx.x) >> 5;
    int lane = threadIdx.x & 31;
    if (w >= (int)C) return;

    unsigned long long me = g_cand[w];
    int cnt = 0;
    int j = lane;
    for (; j + 96 < (int)C; j += 128) {
        unsigned long long a = g_cand[j];
        unsigned long long b = g_cand[j + 32];
        unsigned long long c = g_cand[j + 64];
        unsigned long long d = g_cand[j + 96];
        cnt += (a > me) + (b > me) + (c > me) + (d > me);
    }
    for (; j < (int)C; j += 32)
        cnt += (g_cand[j] > me);

    #pragma unroll
    for (int off = 16; off > 0; off >>= 1)
        cnt += __shfl_xor_sync(0xFFFFFFFFu, cnt, off);   // all lanes get rank

    if (cnt < kk) {
        unsigned int key = (unsigned int)(me >> 32);
        unsigned int idx = 0xFFFFFFFFu - (unsigned int)(me & 0xFFFFFFFFull);
        float tv = tanhf(fdec(key));
        const float4* __restrict__ src = reinterpret_cast<const float4*>(x) +
                                         (size_t)idx * 32;
        float4* __restrict__ dst = reinterpret_cast<float4*>(out) +
                                   (size_t)cnt * 32;
        float4 v = src[lane];
        v.x *= tv; v.y *= tv; v.z *= tv; v.w *= tv;
        dst[lane] = v;
    }
}

// ----------------------------------------------------------------
extern "C" void kernel_launch(void* const* d_in, const int* in_sizes, int n_in,
                              void* d_out, int out_size) {
    const float* x = (const float*)d_in[0];
    const float* p = (const float*)d_in[1];
    float* out = (float*)d_out;

    int n  = in_sizes[0] / DIM;      // 500000
    int kk = out_size / DIM;         // 2048

    zeroA_kernel<<<32, 256>>>();
    zeroB_kernel<<<32, 256>>>();
    zeroC_kernel<<<1, 1>>>();
    score_kernel<<<148 * 2, 256>>>(x, p, n);     // persistent, 2 blocks/SM
    coarse_thresh_kernel<<<256, 256>>>(kk);
    int nq = n >> 2;
    compact_kernel<<<(nq + 255) / 256, 256>>>(n);
    rank_gather_kernel<<<(CAP * 32) / 256, 256>>>(x, out, kk);
}

// round 11
// speedup vs baseline: 1.0637x; 1.0353x over previous
#include <cuda_runtime.h>
#include <cuda_bf16.h>
#include <math.h>
#include <stdint.h>

// Problem shape (fixed by dataset): N=500000, D=128, K=2048
#define MAXN   500000
#define DIM    128
#define NBINS  65536
#define CAP    6144
#define MAXK   2048

#define TILE_ROWS   128
#define ROW_BYTES   (DIM * 4)                 // 512
#define TILE_BYTES  (TILE_ROWS * ROW_BYTES)   // 65536
#define STAGES      3
#define SCORE_BLOCKS  148
#define SCORE_THREADS 256

static __device__ unsigned int        g_keys[MAXN];
static __device__ unsigned int        g_hist[NBINS];
static __device__ unsigned int        g_coarse[256];
static __device__ unsigned int        g_counter;
static __device__ unsigned int        g_done;       // epoch counter (never reset)
static __device__ unsigned int        g_thresh;
static __device__ unsigned long long  g_cand[CAP];

// ---------------- small PTX helpers (from ptx_helpers.cuh) ----------------
__device__ __forceinline__ uint32_t smem_u32(const void* p_) {
    uint32_t a;
    asm("{ .reg .u64 t; cvta.to.shared.u64 t, %1; cvt.u32.u64 %0, t; }"
        : "=r"(a) : "l"(p_));
    return a;
}
#define MBAR_INIT(addr, cnt) \
    asm volatile("mbarrier.init.shared.b64 [%0], %1;" :: "r"(addr), "r"(cnt) : "memory")
#define MBAR_EXPECT_TX(addr, bytes) \
    asm volatile("mbarrier.arrive.expect_tx.shared.b64 _, [%0], %1;" \
                 :: "r"(addr), "r"(bytes) : "memory")
#define MBAR_WAIT(addr, par) do {                                         \
    uint32_t _m = (addr); uint32_t _p = (par); uint32_t _d;               \
    asm volatile("{\n\t.reg .pred p;\n\t"                                 \
        "mbarrier.try_wait.parity.acquire.cta.shared::cta.b64 p, [%1], %2;\n\t" \
        "selp.b32 %0, 1, 0, p;\n\t}"                                      \
        : "=r"(_d) : "r"(_m), "r"(_p) : "memory");                        \
    if (!_d) {                                                            \
        asm volatile("{\n\t.reg .pred P1;\n\t"                            \
            "W_%=:\n\t"                                                   \
            "mbarrier.try_wait.parity.acquire.cta.shared::cta.b64 P1, [%0], %1, 0x989680;\n\t" \
            "@P1 bra.uni D_%=;\n\t"                                       \
            "bra.uni W_%=;\n\t"                                           \
            "D_%=:\n\t}" :: "r"(_m), "r"(_p) : "memory");                 \
    }                                                                     \
} while (0)
__device__ __forceinline__ void bulk_g2s(uint32_t dst_smem, const void* src,
                                         uint32_t bytes, uint32_t mbar) {
    asm volatile(
        "cp.async.bulk.shared::cluster.global.mbarrier::complete_tx::bytes "
        "[%0], [%1], %2, [%3];"
        :: "r"(dst_smem), "l"(src), "r"(bytes), "r"(mbar) : "memory");
}

// order-preserving float -> u32 key
__device__ __forceinline__ unsigned int fkey(float f) {
    unsigned int b = __float_as_uint(f);
    return (b & 0x80000000u) ? ~b : (b | 0x80000000u);
}
__device__ __forceinline__ float fdec(unsigned int k) {
    unsigned int b = (k & 0x80000000u) ? (k ^ 0x80000000u) : ~k;
    return __uint_as_float(b);
}

// ---------------------------------------------------------------- kernel 1
// TMA-pipelined score: 148 persistent blocks, 3-stage 64KB smem pipeline.
// Thread 0 produces via cp.async.bulk; 8 warps consume 16 rows each.
__global__ void __launch_bounds__(SCORE_THREADS, 1)
score_kernel(const float* __restrict__ x, const float* __restrict__ p, int n) {
    __shared__ __align__(8) unsigned long long mbar[STAGES];
    extern __shared__ char tiles[];               // STAGES * TILE_BYTES

    const int tid  = threadIdx.x;
    const int lane = tid & 31;
    const int w    = tid >> 5;
    const int bid  = blockIdx.x;

    // ||p|| (every warp)
    float4 p4 = reinterpret_cast<const float4*>(p)[lane];
    float sq = p4.x * p4.x + p4.y * p4.y + p4.z * p4.z + p4.w * p4.w;
    #pragma unroll
    for (int off = 16; off > 0; off >>= 1)
        sq += __shfl_xor_sync(0xFFFFFFFFu, sq, off);
    const float inv = rsqrtf(sq);

    const bool b4 = (lane & 16) != 0;
    const bool b3 = (lane & 8)  != 0;
    const bool b2 = (lane & 4)  != 0;

    const uint32_t smem_base = smem_u32(tiles);
    const uint32_t mbar_base = smem_u32(mbar);

    const int ntiles = (n + TILE_ROWS - 1) / TILE_ROWS;      // 3907
    // tiles owned by this block: bid, bid+148, ...
    const int myT = (bid < ntiles) ? ((ntiles - 1 - bid) / SCORE_BLOCKS + 1) : 0;

    if (tid == 0) {
        #pragma unroll
        for (int s = 0; s < STAGES; s++) MBAR_INIT(mbar_base + 8 * s, 1);
    }
    __syncthreads();

    // prologue: fill the pipeline
    if (tid == 0) {
        for (int j = 0; j < STAGES && j < myT; j++) {
            int tile = bid + j * SCORE_BLOCKS;
            int rows = min(TILE_ROWS, n - tile * TILE_ROWS);
            uint32_t bytes = (uint32_t)rows * ROW_BYTES;
            MBAR_EXPECT_TX(mbar_base + 8 * j, bytes);
            bulk_g2s(smem_base + j * TILE_BYTES,
                     x + (size_t)tile * TILE_ROWS * DIM, bytes,
                     mbar_base + 8 * j);
        }
    }

    for (int j = 0; j < myT; j++) {
        const int s   = j % STAGES;
        const int par = (j / STAGES) & 1;
        MBAR_WAIT(mbar_base + 8 * s, par);

        const int tile = bid + j * SCORE_BLOCKS;
        const int rows = min(TILE_ROWS, n - tile * TILE_ROWS); // 128 or 32
        const char* tbase = tiles + s * TILE_BYTES;

        // each warp: up to 2 groups of 8 rows
        #pragma unroll
        for (int grp = 0; grp < 2; grp++) {
            const int gr = w * 16 + grp * 8;        // row within tile
            if (gr < rows) {
                const char* rb = tbase + gr * ROW_BYTES;
                float4 v[8];
                #pragma unroll
                for (int r = 0; r < 8; r++)
                    v[r] = *reinterpret_cast<const float4*>(
                               rb + r * ROW_BYTES + lane * 16);
                float d[8];
                #pragma unroll
                for (int r = 0; r < 8; r++)
                    d[r] = fmaf(v[r].x, p4.x, fmaf(v[r].y, p4.y,
                           fmaf(v[r].z, p4.z, v[r].w * p4.w)));
                // packed tree reduction: 8 regs -> 1, 9 shuffles
                float e[4];
                #pragma unroll
                for (int k = 0; k < 4; k++) {
                    float keep = b4 ? d[2*k+1] : d[2*k];
                    float send = b4 ? d[2*k]   : d[2*k+1];
                    e[k] = keep + __shfl_xor_sync(0xFFFFFFFFu, send, 16);
                }
                float f[2];
                #pragma unroll
                for (int jj = 0; jj < 2; jj++) {
                    float keep = b3 ? e[2*jj+1] : e[2*jj];
                    float send = b3 ? e[2*jj]   : e[2*jj+1];
                    f[jj] = keep + __shfl_xor_sync(0xFFFFFFFFu, send, 8);
                }
                float g;
                {
                    float keep = b2 ? f[1] : f[0];
                    float send = b2 ? f[0] : f[1];
                    g = keep + __shfl_xor_sync(0xFFFFFFFFu, send, 4);
                }
                g += __shfl_xor_sync(0xFFFFFFFFu, g, 2);
                g += __shfl_xor_sync(0xFFFFFFFFu, g, 1);

                if ((lane & 3) == 0) {
                    int m = lane >> 2;
                    int r = ((m & 1) << 2) | (m & 2) | ((m >> 2) & 1);
                    int row = tile * TILE_ROWS + gr + r;     // always < n here
                    unsigned int key = fkey(g * inv);
                    g_keys[row] = key;
                    atomicAdd(&g_hist[key >> 16], 1u);
                }
            }
        }
        __syncthreads();            // all warps done reading stage s

        if (tid == 0) {
            int jn = j + STAGES;
            if (jn < myT) {
                int tn = bid + jn * SCORE_BLOCKS;
                int rn = min(TILE_ROWS, n - tn * TILE_ROWS);
                uint32_t bytes = (uint32_t)rn * ROW_BYTES;
                MBAR_EXPECT_TX(mbar_base + 8 * s, bytes);
                bulk_g2s(smem_base + s * TILE_BYTES,
                         x + (size_t)tn * TILE_ROWS * DIM, bytes,
                         mbar_base + 8 * s);
            }
        }
    }
}

// ---------------------------------------------------------------- kernel 2
// fused coarse sums + threshold search; epoch-based last-block detection.
// Also resets g_counter for this replay (ordered before compact).
__global__ void coarse_thresh_kernel(int kk) {
    __shared__ unsigned int sh[256];
    __shared__ unsigned int suf[256];
    __shared__ int s_last;
    __shared__ int s_ch;
    __shared__ unsigned int s_above;

    int t = threadIdx.x;
    int b = blockIdx.x;

    if (b == 0 && t == 0) g_counter = 0u;

    sh[t] = g_hist[b * 256 + t];
    __syncthreads();
    #pragma unroll
    for (int off = 128; off >= 1; off >>= 1) {
        if (t < off) sh[t] += sh[t + off];
        __syncthreads();
    }
    if (t == 0) {
        g_coarse[b] = sh[0];
        __threadfence();
        unsigned int d = atomicAdd(&g_done, 1u);
        s_last = ((d & 255u) == 255u);        // epoch: no reset needed
    }
    __syncthreads();
    if (!s_last) return;

    __threadfence();
    suf[t] = g_coarse[t];
    __syncthreads();
    #pragma unroll
    for (int off = 1; off < 256; off <<= 1) {
        unsigned int u = (t + off < 256) ? suf[t + off] : 0u;
        __syncthreads();
        suf[t] += u;
        __syncthreads();
    }
    if (suf[t] >= (unsigned int)kk &&
        (t == 255 || suf[t + 1] < (unsigned int)kk)) {
        s_ch = t;
        s_above = (t == 255) ? 0u : suf[t + 1];
    }
    __syncthreads();

    int ch = s_ch;
    unsigned int above = s_above;

    sh[t] = g_hist[ch * 256 + t];
    __syncthreads();
    #pragma unroll
    for (int off = 1; off < 256; off <<= 1) {
        unsigned int u = (t + off < 256) ? sh[t + off] : 0u;
        __syncthreads();
        sh[t] += u;
        __syncthreads();
    }
    if (above + sh[t] >= (unsigned int)kk &&
        (t == 255 || above + sh[t + 1] < (unsigned int)kk)) {
        g_thresh = ((unsigned int)(ch * 256 + t)) << 16;
    }
}

// ---------------------------------------------------------------- kernel 3
// compact (warp-aggregated atomic) + re-zero hist for the next replay
__global__ void compact_kernel(int n) {
    const unsigned int thr = g_thresh;
    const int nq = n >> 2;                       // n % 4 == 0
    int i = blockIdx.x * blockDim.x + threadIdx.x;
    int lane = threadIdx.x & 31;

    // re-zero histogram (64K uints = 16K uint4) for the next graph replay
    if (i < NBINS / 4)
        reinterpret_cast<uint4*>(g_hist)[i] = make_uint4(0u, 0u, 0u, 0u);

    uint4 k = (i < nq) ? reinterpret_cast<const uint4*>(g_keys)[i]
                       : make_uint4(0u, 0u, 0u, 0u);
    unsigned int kv[4] = {k.x, k.y, k.z, k.w};
    unsigned int cnt = 0;
    #pragma unroll
    for (int e = 0; e < 4; e++) cnt += (kv[e] >= thr);

    if (__ballot_sync(0xFFFFFFFFu, cnt > 0) == 0u) return;

    unsigned int pre = cnt;
    #pragma unroll
    for (int off = 1; off < 32; off <<= 1) {
        unsigned int u = __shfl_up_sync(0xFFFFFFFFu, pre, off);
        if (lane >= off) pre += u;
    }
    unsigned int tot  = __shfl_sync(0xFFFFFFFFu, pre, 31);
    unsigned int excl = pre - cnt;

    unsigned int base = 0;
    if (lane == 31) base = atomicAdd(&g_counter, tot);
    base = __shfl_sync(0xFFFFFFFFu, base, 31);

    unsigned int pos = base + excl;
    unsigned int bi = (unsigned int)(i << 2);
    #pragma unroll
    for (int e = 0; e < 4; e++) {
        if (kv[e] >= thr) {
            if (pos < CAP)
                g_cand[pos] = ((unsigned long long)kv[e] << 32) |
                              (0xFFFFFFFFull - (bi + e));
            pos++;
        }
    }
}

// ---------------------------------------------------------------- kernel 4
// fused rank-by-counting + gather: warp per candidate; writes out[rank] row
__global__ void rank_gather_kernel(const float* __restrict__ x,
                                   float* __restrict__ out, int kk) {
    unsigned int C = g_counter; if (C > CAP) C = CAP;
    int w    = (blockIdx.x * blockDim.x + threadIdx.x) >> 5;
    int lane = threadIdx.x & 31;
    if (w >= (int)C) return;

    unsigned long long me = g_cand[w];
    int cnt = 0;
    int j = lane;
    for (; j + 96 < (int)C; j += 128) {
        unsigned long long a = g_cand[j];
        unsigned long long b = g_cand[j + 32];
        unsigned long long c = g_cand[j + 64];
        unsigned long long d = g_cand[j + 96];
        cnt += (a > me) + (b > me) + (c > me) + (d > me);
    }
    for (; j < (int)C; j += 32)
        cnt += (g_cand[j] > me);

    #pragma unroll
    for (int off = 16; off > 0; off >>= 1)
        cnt += __shfl_xor_sync(0xFFFFFFFFu, cnt, off);   // all lanes get rank

    if (cnt < kk) {
        unsigned int key = (unsigned int)(me >> 32);
        unsigned int idx = 0xFFFFFFFFu - (unsigned int)(me & 0xFFFFFFFFull);
        float tv = tanhf(fdec(key));
        const float4* __restrict__ src = reinterpret_cast<const float4*>(x) +
                                         (size_t)idx * 32;
        float4* __restrict__ dst = reinterpret_cast<float4*>(out) +
                                   (size_t)cnt * 32;
        float4 v = src[lane];
        v.x *= tv; v.y *= tv; v.z *= tv; v.w *= tv;
        dst[lane] = v;
    }
}

// ----------------------------------------------------------------
extern "C" void kernel_launch(void* const* d_in, const int* in_sizes, int n_in,
                              void* d_out, int out_size) {
    const float* x = (const float*)d_in[0];
    const float* p = (const float*)d_in[1];
    float* out = (float*)d_out;

    int n  = in_sizes[0] / DIM;      // 500000
    int kk = out_size / DIM;         // 2048

    cudaFuncSetAttribute(score_kernel,
                         cudaFuncAttributeMaxDynamicSharedMemorySize,
                         STAGES * TILE_BYTES);

    score_kernel<<<SCORE_BLOCKS, SCORE_THREADS, STAGES * TILE_BYTES>>>(x, p, n);
    coarse_thresh_kernel<<<256, 256>>>(kk);
    int nq = n >> 2;
    compact_kernel<<<(nq + 255) / 256, 256>>>(n);
    rank_gather_kernel<<<(CAP * 32) / 256, 256>>>(x, out, kk);
}